// round 11
// baseline (speedup 1.0000x reference)
#include <cuda_runtime.h>
#include <cuda_bf16.h>

#define NN 32768
#define NB 64
#define E  256
#define NSC 4
#define NH 8
#define HD 32
#define BN_EPS 1e-5f
#define QS 0.17677669529663687f

// packed bf16 hi/lo word tensors (word = 2 adjacent elements)
__device__ unsigned g_hh[(size_t)NN * 128], g_hl[(size_t)NN * 128];
__device__ unsigned g_qh[(size_t)NN * 384], g_ql[(size_t)NN * 384];   // Q pre-scaled
__device__ unsigned g_ch[(size_t)NN * 128], g_cl[(size_t)NN * 128];
__device__ float g_att[(size_t)NN * E];
__device__ int   g_counts[NB], g_starts[NB], g_maxM, g_stride;
__device__ float g_psum[256 * E], g_psumsq[256 * E];
__device__ float g_bnscale[E], g_bnshift[E];
#define W_WORDS 163840          /* words: W_in 98304 | W_out 32768 | Ws^T 32768 */
__device__ unsigned g_Whi[W_WORDS], g_Wlo[W_WORDS];

__device__ __forceinline__ unsigned short f2bs(float x)
{ return __bfloat16_as_ushort(__float2bfloat16_rn(x)); }
__device__ __forceinline__ float bs2f(unsigned short s)
{ return __bfloat162float(__ushort_as_bfloat16(s)); }
__device__ __forceinline__ float blo(unsigned u) { return bs2f((unsigned short)(u & 0xffff)); }
__device__ __forceinline__ float bhi(unsigned u) { return bs2f((unsigned short)(u >> 16)); }
__device__ __forceinline__ void split2(float a, float b, unsigned& hi, unsigned& lo)
{
    unsigned short ha = f2bs(a), hb = f2bs(b);
    unsigned short la = f2bs(a - bs2f(ha)), lb = f2bs(b - bs2f(hb));
    hi = (unsigned)ha | ((unsigned)hb << 16);
    lo = (unsigned)la | ((unsigned)lb << 16);
}
__device__ __forceinline__ void mma16(float* c, const unsigned* a, unsigned b0, unsigned b1)
{
    asm volatile("mma.sync.aligned.m16n8k16.row.col.f32.bf16.bf16.f32 "
                 "{%0,%1,%2,%3}, {%4,%5,%6,%7}, {%8,%9}, {%0,%1,%2,%3};"
                 : "+f"(c[0]), "+f"(c[1]), "+f"(c[2]), "+f"(c[3])
                 : "r"(a[0]), "r"(a[1]), "r"(a[2]), "r"(a[3]), "r"(b0), "r"(b1));
}

// ---- batch bookkeeping (int32 vs int64 sniffing) ----
__global__ void k_detect(const int* __restrict__ b32)
{
    __shared__ int any;
    if (threadIdx.x == 0) any = 0;
    __syncthreads();
    int loc = 0;
    for (int i = threadIdx.x; i < NN / 2; i += blockDim.x)
        if (b32[2 * i + 1] != 0) loc = 1;
    if (loc) atomicExch(&any, 1);
    __syncthreads();
    if (threadIdx.x == 0) {
        g_stride = any ? 1 : 2;
        for (int b = 0; b < NB; b++) g_counts[b] = 0;
    }
}
__global__ void k_hist(const int* __restrict__ b32)
{
    __shared__ int hc[NB];
    int t = threadIdx.x;
    if (t < NB) hc[t] = 0;
    __syncthreads();
    int n = blockIdx.x * blockDim.x + t;
    atomicAdd(&hc[b32[(size_t)n * g_stride] & (NB - 1)], 1);
    __syncthreads();
    if (t < NB) atomicAdd(&g_counts[t], hc[t]);
}
__global__ void k_scan()
{
    int run = 0, mx = 0;
    for (int b = 0; b < NB; b++) {
        g_starts[b] = run;
        int c = g_counts[b];
        run += c;
        if (c > mx) mx = c;
    }
    g_maxM = mx;
}

// ---- weight split+pack prep: words of [W_in | W_out | Ws^T(s,o,k)] ----
__global__ void k_split_w(const float* __restrict__ W_in, const float* __restrict__ W_out,
                          const float* __restrict__ Ws)
{
    int i = blockIdx.x * blockDim.x + threadIdx.x;
    if (i >= W_WORDS) return;
    int e = 2 * i;
    float w0, w1;
    if (e < 196608) { w0 = W_in[e]; w1 = W_in[e + 1]; }
    else if (e < 262144) { w0 = W_out[e - 196608]; w1 = W_out[e - 196607]; }
    else {
        int j = e - 262144, s = j >> 14, rem = j & 16383;
        int o = rem >> 8, k = rem & 255;
        w0 = Ws[s * 16384 + k * 64 + o];
        w1 = Ws[s * 16384 + (k + 1) * 64 + o];
    }
    split2(w0, w1, g_Whi[i], g_Wlo[i]);
}

// ---- bf16x3 GEMM on pre-split A: C[NN,NTOT] = A[NN,256] * W^T + bias ----
// block 64m x 128n, 8 warps (4 wm x 2 wn), warp tile 16x64; k-chunks of 32.
// OUTMODE 0: f32 out (Cf).  OUTMODE 1: packed hi/lo out + Q-scale on cols<256.
template<int NTOT, int OUTMODE>
__device__ __forceinline__ void gemm_pk_body(
    const unsigned* __restrict__ Ahi, const unsigned* __restrict__ Alo,
    const unsigned* __restrict__ Whi, const unsigned* __restrict__ Wlo,
    const float* __restrict__ bias, float* __restrict__ Cf,
    unsigned* __restrict__ Chi, unsigned* __restrict__ Clo)
{
    __shared__ unsigned Ah[64][20], Al[64][20];
    __shared__ unsigned Bh[128][20], Bl[128][20];
    const int tid = threadIdx.x, wid = tid >> 5, lane = tid & 31;
    const int g = lane >> 2, t4 = lane & 3, wm = wid >> 1, wn = wid & 1;
    const int m0 = blockIdx.x * 64, n0 = blockIdx.y * 128;

    float acc[8][4] = {};
    for (int ch = 0; ch < 8; ch++) {
        __syncthreads();
        for (int i = tid; i < 512; i += 256) {            // A chunk 64 x 16 words
            int r = i >> 3, w2 = (i & 7) << 1;
            size_t ga = (size_t)(m0 + r) * 128 + ch * 16 + w2;
            *(uint2*)&Ah[r][w2] = *(const uint2*)(Ahi + ga);
            *(uint2*)&Al[r][w2] = *(const uint2*)(Alo + ga);
        }
        for (int i = tid; i < 1024; i += 256) {           // B chunk 128 x 16 words
            int r = i >> 3, w2 = (i & 7) << 1;
            size_t go = (size_t)(n0 + r) * 128 + ch * 16 + w2;
            *(uint2*)&Bh[r][w2] = *(const uint2*)(Whi + go);
            *(uint2*)&Bl[r][w2] = *(const uint2*)(Wlo + go);
        }
        __syncthreads();
#pragma unroll
        for (int kk = 0; kk < 2; kk++) {
            const int kw = kk * 8, ra = 16 * wm + g;
            unsigned ah[4], al[4];
            ah[0] = Ah[ra][kw + t4];     ah[1] = Ah[ra + 8][kw + t4];
            ah[2] = Ah[ra][kw + t4 + 4]; ah[3] = Ah[ra + 8][kw + t4 + 4];
            al[0] = Al[ra][kw + t4];     al[1] = Al[ra + 8][kw + t4];
            al[2] = Al[ra][kw + t4 + 4]; al[3] = Al[ra + 8][kw + t4 + 4];
#pragma unroll
            for (int ni = 0; ni < 8; ni++) {
                int n = 64 * wn + 8 * ni + g;
                unsigned bh0 = Bh[n][kw + t4], bh1 = Bh[n][kw + t4 + 4];
                mma16(acc[ni], ah, bh0, bh1);
                mma16(acc[ni], ah, Bl[n][kw + t4], Bl[n][kw + t4 + 4]);
                mma16(acc[ni], al, bh0, bh1);
            }
        }
    }
    const int r1 = m0 + 16 * wm + g;
#pragma unroll
    for (int ni = 0; ni < 8; ni++) {
        int n = n0 + 64 * wn + 8 * ni + 2 * t4;
        float b0 = bias[n], b1 = bias[n + 1];
        float c00 = acc[ni][0] + b0, c01 = acc[ni][1] + b1;
        float c10 = acc[ni][2] + b0, c11 = acc[ni][3] + b1;
        if (OUTMODE == 1) {
            if (n < 256) { c00 *= QS; c01 *= QS; c10 *= QS; c11 *= QS; }
            unsigned hw, lw;
            split2(c00, c01, hw, lw);
            Chi[(size_t)r1 * (NTOT / 2) + n / 2] = hw;
            Clo[(size_t)r1 * (NTOT / 2) + n / 2] = lw;
            split2(c10, c11, hw, lw);
            Chi[(size_t)(r1 + 8) * (NTOT / 2) + n / 2] = hw;
            Clo[(size_t)(r1 + 8) * (NTOT / 2) + n / 2] = lw;
        } else {
            *(float2*)(Cf + (size_t)r1 * NTOT + n)       = make_float2(c00, c01);
            *(float2*)(Cf + (size_t)(r1 + 8) * NTOT + n) = make_float2(c10, c11);
        }
    }
}

__global__ void __launch_bounds__(256) k_gemm_qkv_tc(const float* __restrict__ bias)
{ gemm_pk_body<768, 1>(g_hh, g_hl, g_Whi, g_Wlo, bias, nullptr, g_qh, g_ql); }

__global__ void __launch_bounds__(256) k_gemm_out_tc(const float* __restrict__ bias)
{ gemm_pk_body<256, 0>(g_ch, g_cl, g_Whi + 98304, g_Wlo + 98304, bias, g_att, nullptr, nullptr); }

// ---- scale GEMM: h[:, s*64+o] = (x + spec[s]) * WsT[s] + bs, packed out ----
__global__ void __launch_bounds__(256) k_gemm_scale_tc(
    const float* __restrict__ x, const float* __restrict__ spec,
    const float* __restrict__ bs)
{
    __shared__ unsigned Ah[64][20], Al[64][20];
    __shared__ unsigned Bh[64][20], Bl[64][20];
    const int tid = threadIdx.x, wid = tid >> 5, lane = tid & 31;
    const int g = lane >> 2, t4 = lane & 3, wm = wid >> 1, wn = wid & 1;
    const int m0 = blockIdx.x * 64;

    for (int s = 0; s < NSC; s++) {
        const float* sb = spec + (size_t)s * NN * 256;
        const unsigned* Wsh = g_Whi + 131072 + s * 8192;
        const unsigned* Wsl = g_Wlo + 131072 + s * 8192;
        float acc[4][4] = {};
        for (int ch = 0; ch < 8; ch++) {
            __syncthreads();
            for (int i = tid; i < 512; i += 256) {
                int r = i >> 3, fc = (i & 7) << 2, w0 = (i & 7) << 1;
                size_t go = (size_t)(m0 + r) * 256 + ch * 32 + fc;
                float4 a = *(const float4*)(x + go);
                float4 b = *(const float4*)(sb + go);
                a.x += b.x; a.y += b.y; a.z += b.z; a.w += b.w;
                split2(a.x, a.y, Ah[r][w0], Al[r][w0]);
                split2(a.z, a.w, Ah[r][w0 + 1], Al[r][w0 + 1]);
            }
            for (int i = tid; i < 512; i += 256) {
                int r = i >> 3, w2 = (i & 7) << 1;
                size_t go = (size_t)r * 128 + ch * 16 + w2;
                *(uint2*)&Bh[r][w2] = *(const uint2*)(Wsh + go);
                *(uint2*)&Bl[r][w2] = *(const uint2*)(Wsl + go);
            }
            __syncthreads();
#pragma unroll
            for (int kk = 0; kk < 2; kk++) {
                const int kw = kk * 8, ra = 16 * wm + g;
                unsigned ah[4], al[4];
                ah[0] = Ah[ra][kw + t4];     ah[1] = Ah[ra + 8][kw + t4];
                ah[2] = Ah[ra][kw + t4 + 4]; ah[3] = Ah[ra + 8][kw + t4 + 4];
                al[0] = Al[ra][kw + t4];     al[1] = Al[ra + 8][kw + t4];
                al[2] = Al[ra][kw + t4 + 4]; al[3] = Al[ra + 8][kw + t4 + 4];
#pragma unroll
                for (int ni = 0; ni < 4; ni++) {
                    int n = 32 * wn + 8 * ni + g;
                    unsigned bh0 = Bh[n][kw + t4], bh1 = Bh[n][kw + t4 + 4];
                    mma16(acc[ni], ah, bh0, bh1);
                    mma16(acc[ni], ah, Bl[n][kw + t4], Bl[n][kw + t4 + 4]);
                    mma16(acc[ni], al, bh0, bh1);
                }
            }
        }
        const int r1 = m0 + 16 * wm + g;
#pragma unroll
        for (int ni = 0; ni < 4; ni++) {
            int col = 32 * wn + 8 * ni + 2 * t4, n = s * 64 + col;
            float b0 = bs[n], b1 = bs[n + 1];
            unsigned hw, lw;
            split2(acc[ni][0] + b0, acc[ni][1] + b1, hw, lw);
            g_hh[(size_t)r1 * 128 + n / 2] = hw;
            g_hl[(size_t)r1 * 128 + n / 2] = lw;
            split2(acc[ni][2] + b0, acc[ni][3] + b1, hw, lw);
            g_hh[(size_t)(r1 + 8) * 128 + n / 2] = hw;
            g_hl[(size_t)(r1 + 8) * 128 + n / 2] = lw;
        }
        __syncthreads();
    }
}

// ---- flash attention (bf16x3): 128 threads, Q tile 64, K/V tile 64 ----
// Inputs pre-split/packed (Q pre-scaled). Pad keys of the reference (no
// key-padding mask) folded analytically with multiplicity (maxM - c).
__global__ void __launch_bounds__(128) k_attn_tc(const float* __restrict__ b_in)
{
    __shared__ unsigned Qh[64][20], Ql[64][20];
    __shared__ unsigned Kh[64][20], Kl[64][20];
    __shared__ unsigned Vh[32][36], Vl[32][36];      // [d][key-pair words]
    __shared__ unsigned Pm[4][16][36], Pw2[4][16][36];
    __shared__ float kp[32], vp[32];

    const int b = blockIdx.x, h = blockIdx.y;
    const int tid = threadIdx.x, wid = tid >> 5, lane = tid & 31;
    const int g = lane >> 2, t4 = lane & 3;
    const int c = g_counts[b], start = g_starts[b];
    const float npadf = (float)(g_maxM - c);

    if (tid < 32) { kp[tid] = b_in[E + h * HD + tid]; vp[tid] = b_in[2 * E + h * HD + tid]; }

    for (int q0 = 0; q0 < c; q0 += 64) {
        __syncthreads();
        for (int i = tid; i < 512; i += 128) {            // Q tile 64 x 16 words
            int r = i >> 3, w2 = (i & 7) << 1, row = q0 + r;
            uint2 u = make_uint2(0, 0), l = make_uint2(0, 0);
            if (row < c) {
                size_t ga = (size_t)(start + row) * 384 + h * 16 + w2;
                u = *(const uint2*)(g_qh + ga);
                l = *(const uint2*)(g_ql + ga);
            }
            *(uint2*)&Qh[r][w2] = u;
            *(uint2*)&Ql[r][w2] = l;
        }
        float m1 = -1e30f, m2 = -1e30f, l1 = 0.f, l2 = 0.f;
        float acc[4][4] = {};

        for (int kb = 0; kb < c; kb += 64) {
            __syncthreads();
            for (int i = tid; i < 512; i += 128) {        // K tile 64 x 16 words
                int r = i >> 3, w2 = (i & 7) << 1, key = kb + r;
                uint2 u = make_uint2(0, 0), l = make_uint2(0, 0);
                if (key < c) {
                    size_t ga = (size_t)(start + key) * 384 + 128 + h * 16 + w2;
                    u = *(const uint2*)(g_qh + ga);
                    l = *(const uint2*)(g_ql + ga);
                }
                *(uint2*)&Kh[r][w2] = u;
                *(uint2*)&Kl[r][w2] = l;
            }
            for (int i = tid; i < 1024; i += 128) {       // V tile: transpose to [d][key]
                int r = i >> 4, w = i & 15, key = kb + r;
                unsigned u = 0, l = 0;
                if (key < c) {
                    size_t ga = (size_t)(start + key) * 384 + 256 + h * 16 + w;
                    u = g_qh[ga];
                    l = g_ql[ga];
                }
                ((unsigned short*)Vh[2 * w])[r]     = (unsigned short)(u & 0xffff);
                ((unsigned short*)Vh[2 * w + 1])[r] = (unsigned short)(u >> 16);
                ((unsigned short*)Vl[2 * w])[r]     = (unsigned short)(l & 0xffff);
                ((unsigned short*)Vl[2 * w + 1])[r] = (unsigned short)(l >> 16);
            }
            __syncthreads();

            float s[8][4] = {};
            const int qr = 16 * wid + g;
#pragma unroll
            for (int kk = 0; kk < 2; kk++) {
                const int kw = kk * 8;
                unsigned ah[4], al[4];
                ah[0] = Qh[qr][kw + t4];     ah[1] = Qh[qr + 8][kw + t4];
                ah[2] = Qh[qr][kw + t4 + 4]; ah[3] = Qh[qr + 8][kw + t4 + 4];
                al[0] = Ql[qr][kw + t4];     al[1] = Ql[qr + 8][kw + t4];
                al[2] = Ql[qr][kw + t4 + 4]; al[3] = Ql[qr + 8][kw + t4 + 4];
#pragma unroll
                for (int ni = 0; ni < 8; ni++) {
                    int key = 8 * ni + g;
                    unsigned bh0 = Kh[key][kw + t4], bh1 = Kh[key][kw + t4 + 4];
                    mma16(s[ni], ah, bh0, bh1);
                    mma16(s[ni], ah, Kl[key][kw + t4], Kl[key][kw + t4 + 4]);
                    mma16(s[ni], al, bh0, bh1);
                }
            }
#pragma unroll
            for (int ni = 0; ni < 8; ni++) {
                int col = kb + 8 * ni + 2 * t4;
                if (col >= c)     { s[ni][0] = -1e30f; s[ni][2] = -1e30f; }
                if (col + 1 >= c) { s[ni][1] = -1e30f; s[ni][3] = -1e30f; }
            }
            float mx1 = -1e30f, mx2 = -1e30f;
#pragma unroll
            for (int ni = 0; ni < 8; ni++) {
                mx1 = fmaxf(mx1, fmaxf(s[ni][0], s[ni][1]));
                mx2 = fmaxf(mx2, fmaxf(s[ni][2], s[ni][3]));
            }
            mx1 = fmaxf(mx1, __shfl_xor_sync(~0u, mx1, 1)); mx1 = fmaxf(mx1, __shfl_xor_sync(~0u, mx1, 2));
            mx2 = fmaxf(mx2, __shfl_xor_sync(~0u, mx2, 1)); mx2 = fmaxf(mx2, __shfl_xor_sync(~0u, mx2, 2));
            float nm1 = fmaxf(m1, mx1), nm2 = fmaxf(m2, mx2);
            float corr1 = __expf(m1 - nm1), corr2 = __expf(m2 - nm2);
            float sum1 = 0.f, sum2 = 0.f;
#pragma unroll
            for (int ni = 0; ni < 8; ni++) {
                float p0 = __expf(s[ni][0] - nm1), p1 = __expf(s[ni][1] - nm1);
                float p2 = __expf(s[ni][2] - nm2), p3 = __expf(s[ni][3] - nm2);
                sum1 += p0 + p1; sum2 += p2 + p3;
                int w = 4 * ni + t4;
                split2(p0, p1, Pm[wid][g][w], Pw2[wid][g][w]);
                split2(p2, p3, Pm[wid][g + 8][w], Pw2[wid][g + 8][w]);
            }
            sum1 += __shfl_xor_sync(~0u, sum1, 1); sum1 += __shfl_xor_sync(~0u, sum1, 2);
            sum2 += __shfl_xor_sync(~0u, sum2, 1); sum2 += __shfl_xor_sync(~0u, sum2, 2);
            l1 = l1 * corr1 + sum1; l2 = l2 * corr2 + sum2;
#pragma unroll
            for (int nd = 0; nd < 4; nd++) {
                acc[nd][0] *= corr1; acc[nd][1] *= corr1;
                acc[nd][2] *= corr2; acc[nd][3] *= corr2;
            }
            m1 = nm1; m2 = nm2;
            __syncwarp();
#pragma unroll
            for (int kk = 0; kk < 4; kk++) {
                const int kw = kk * 8;
                unsigned ph[4], pl[4];
                ph[0] = Pm[wid][g][kw + t4];     ph[1] = Pm[wid][g + 8][kw + t4];
                ph[2] = Pm[wid][g][kw + t4 + 4]; ph[3] = Pm[wid][g + 8][kw + t4 + 4];
                pl[0] = Pw2[wid][g][kw + t4];     pl[1] = Pw2[wid][g + 8][kw + t4];
                pl[2] = Pw2[wid][g][kw + t4 + 4]; pl[3] = Pw2[wid][g + 8][kw + t4 + 4];
#pragma unroll
                for (int nd = 0; nd < 4; nd++) {
                    int d = 8 * nd + g;
                    unsigned vh0 = Vh[d][kw + t4], vh1 = Vh[d][kw + t4 + 4];
                    mma16(acc[nd], ph, vh0, vh1);
                    mma16(acc[nd], ph, Vl[d][kw + t4], Vl[d][kw + t4 + 4]);
                    mma16(acc[nd], pl, vh0, vh1);
                }
            }
            __syncwarp();
        }

        if (npadf > 0.f) {
            const int qr = 16 * wid + g;
            float d1 = 0.f, d2 = 0.f;
#pragma unroll
            for (int jw = 0; jw < 4; jw++) {
                int w = t4 + jw * 4;
                unsigned uh1 = Qh[qr][w], ul1 = Ql[qr][w];
                unsigned uh2 = Qh[qr + 8][w], ul2 = Ql[qr + 8][w];
                d1 += (blo(uh1) + blo(ul1)) * kp[2 * w] + (bhi(uh1) + bhi(ul1)) * kp[2 * w + 1];
                d2 += (blo(uh2) + blo(ul2)) * kp[2 * w] + (bhi(uh2) + bhi(ul2)) * kp[2 * w + 1];
            }
            d1 += __shfl_xor_sync(~0u, d1, 1); d1 += __shfl_xor_sync(~0u, d1, 2);
            d2 += __shfl_xor_sync(~0u, d2, 1); d2 += __shfl_xor_sync(~0u, d2, 2);
            float nm1 = fmaxf(m1, d1), nm2 = fmaxf(m2, d2);
            float corr1 = __expf(m1 - nm1), corr2 = __expf(m2 - nm2);
            float w1 = __expf(d1 - nm1) * npadf, w2 = __expf(d2 - nm2) * npadf;
            l1 = l1 * corr1 + w1; l2 = l2 * corr2 + w2;
#pragma unroll
            for (int nd = 0; nd < 4; nd++) {
                int d0 = 8 * nd + 2 * t4;
                acc[nd][0] = acc[nd][0] * corr1 + w1 * vp[d0];
                acc[nd][1] = acc[nd][1] * corr1 + w1 * vp[d0 + 1];
                acc[nd][2] = acc[nd][2] * corr2 + w2 * vp[d0];
                acc[nd][3] = acc[nd][3] * corr2 + w2 * vp[d0 + 1];
            }
        }
        float inv1 = 1.f / l1, inv2 = 1.f / l2;
        int row1 = q0 + 16 * wid + g, row2 = row1 + 8;
#pragma unroll
        for (int nd = 0; nd < 4; nd++) {
            unsigned hw, lw;
            int wdx = h * 16 + 4 * nd + t4;
            if (row1 < c) {
                split2(acc[nd][0] * inv1, acc[nd][1] * inv1, hw, lw);
                g_ch[(size_t)(start + row1) * 128 + wdx] = hw;
                g_cl[(size_t)(start + row1) * 128 + wdx] = lw;
            }
            if (row2 < c) {
                split2(acc[nd][2] * inv2, acc[nd][3] * inv2, hw, lw);
                g_ch[(size_t)(start + row2) * 128 + wdx] = hw;
                g_cl[(size_t)(start + row2) * 128 + wdx] = lw;
            }
        }
    }
}

// ---- BatchNorm + ReLU ----
__global__ void k_bn_stats()
{
    const int ch = threadIdx.x, r0 = blockIdx.x * 128;
    float s = 0.f, s2 = 0.f;
    for (int r = 0; r < 128; r++) {
        float v = g_att[(size_t)(r0 + r) * E + ch];
        s += v; s2 += v * v;
    }
    g_psum[blockIdx.x * E + ch] = s;
    g_psumsq[blockIdx.x * E + ch] = s2;
}
__global__ void k_bn_finalize(const float* __restrict__ gamma, const float* __restrict__ beta)
{
    const int ch = threadIdx.x;
    float s = 0.f, s2 = 0.f;
    for (int p = 0; p < 256; p++) { s += g_psum[p * E + ch]; s2 += g_psumsq[p * E + ch]; }
    float mean = s / (float)NN;
    float var = s2 / (float)NN - mean * mean;
    float sc = rsqrtf(var + BN_EPS) * gamma[ch];
    g_bnscale[ch] = sc;
    g_bnshift[ch] = beta[ch] - mean * sc;
}
__global__ void k_bn_apply(float* __restrict__ out)
{
    size_t idx = ((size_t)blockIdx.x * blockDim.x + threadIdx.x) * 4;
    int ch = (int)(idx & (E - 1));
    float4 v = *(const float4*)(g_att + idx);
    float4 r;
    r.x = fmaxf(v.x * g_bnscale[ch] + g_bnshift[ch], 0.f);
    r.y = fmaxf(v.y * g_bnscale[ch + 1] + g_bnshift[ch + 1], 0.f);
    r.z = fmaxf(v.z * g_bnscale[ch + 2] + g_bnshift[ch + 2], 0.f);
    r.w = fmaxf(v.w * g_bnscale[ch + 3] + g_bnshift[ch + 3], 0.f);
    *(float4*)(out + idx) = r;
}

extern "C" void kernel_launch(void* const* d_in, const int* in_sizes, int n_in,
                              void* d_out, int out_size)
{
    const float* x        = (const float*)d_in[0];
    const float* spectral = (const float*)d_in[1];
    const float* Ws       = (const float*)d_in[2];
    const float* bs       = (const float*)d_in[3];
    const float* W_in     = (const float*)d_in[4];
    const float* b_in     = (const float*)d_in[5];
    const float* W_out    = (const float*)d_in[6];
    const float* b_out    = (const float*)d_in[7];
    const float* gamma    = (const float*)d_in[8];
    const float* beta     = (const float*)d_in[9];
    const int*   batch32  = (const int*)d_in[10];
    float* out = (float*)d_out;

    k_detect<<<1, 256>>>(batch32);
    k_hist<<<NN / 256, 256>>>(batch32);
    k_scan<<<1, 1>>>();
    k_split_w<<<W_WORDS / 256, 256>>>(W_in, W_out, Ws);

    k_gemm_scale_tc<<<NN / 64, 256>>>(x, spectral, bs);
    k_gemm_qkv_tc<<<dim3(NN / 64, 6), 256>>>(b_in);
    k_attn_tc<<<dim3(NB, NH), 128>>>(b_in);
    k_gemm_out_tc<<<dim3(NN / 64, 2), 256>>>(b_out);

    k_bn_stats<<<256, 256>>>();
    k_bn_finalize<<<1, 256>>>(gamma, beta);
    k_bn_apply<<<(NN * E / 4) / 256, 256>>>(out);
}

// round 12
// speedup vs baseline: 1.2653x; 1.2653x over previous
#include <cuda_runtime.h>
#include <cuda_bf16.h>

#define NN 32768
#define NB 64
#define E  256
#define NSC 4
#define NH 8
#define HD 32
#define BN_EPS 1e-5f

__device__ float g_h  [(size_t)NN * E];
__device__ float g_qkv[(size_t)NN * 3 * E];
__device__ float g_ctx[(size_t)NN * E];
__device__ float g_att[(size_t)NN * E];
__device__ int   g_counts[NB], g_starts[NB], g_maxM, g_stride;
__device__ float g_psum[256 * E], g_psumsq[256 * E];
__device__ float g_bnscale[E], g_bnshift[E];
#define W_TOT 327680            /* floats: W_in 196608 | W_out 65536 | Ws^T 65536 */
#define W_WORDS (W_TOT / 2)     /* packed bf16-pair words */
__device__ unsigned g_Whi[W_WORDS], g_Wlo[W_WORDS];

__device__ __forceinline__ unsigned short f2bs(float x)
{ return __bfloat16_as_ushort(__float2bfloat16_rn(x)); }
__device__ __forceinline__ float bs2f(unsigned short s)
{ return __bfloat162float(__ushort_as_bfloat16(s)); }
__device__ __forceinline__ float blo(unsigned u) { return bs2f((unsigned short)(u & 0xffff)); }
__device__ __forceinline__ float bhi(unsigned u) { return bs2f((unsigned short)(u >> 16)); }
__device__ __forceinline__ void split2(float a, float b, unsigned& hi, unsigned& lo)
{
    unsigned short ha = f2bs(a), hb = f2bs(b);
    unsigned short la = f2bs(a - bs2f(ha)), lb = f2bs(b - bs2f(hb));
    hi = (unsigned)ha | ((unsigned)hb << 16);
    lo = (unsigned)la | ((unsigned)lb << 16);
}
__device__ __forceinline__ void mma16(float* c, const unsigned* a, unsigned b0, unsigned b1)
{
    asm volatile("mma.sync.aligned.m16n8k16.row.col.f32.bf16.bf16.f32 "
                 "{%0,%1,%2,%3}, {%4,%5,%6,%7}, {%8,%9}, {%0,%1,%2,%3};"
                 : "+f"(c[0]), "+f"(c[1]), "+f"(c[2]), "+f"(c[3])
                 : "r"(a[0]), "r"(a[1]), "r"(a[2]), "r"(a[3]), "r"(b0), "r"(b1));
}

// ---- batch bookkeeping (int32 vs int64 sniffing) ----
__global__ void k_detect(const int* __restrict__ b32)
{
    __shared__ int any;
    if (threadIdx.x == 0) any = 0;
    __syncthreads();
    int loc = 0;
    for (int i = threadIdx.x; i < NN / 2; i += blockDim.x)
        if (b32[2 * i + 1] != 0) loc = 1;
    if (loc) atomicExch(&any, 1);
    __syncthreads();
    if (threadIdx.x == 0) {
        g_stride = any ? 1 : 2;
        for (int b = 0; b < NB; b++) g_counts[b] = 0;
    }
}
__global__ void k_hist(const int* __restrict__ b32)
{
    __shared__ int hc[NB];
    int t = threadIdx.x;
    if (t < NB) hc[t] = 0;
    __syncthreads();
    int n = blockIdx.x * blockDim.x + t;
    atomicAdd(&hc[b32[(size_t)n * g_stride] & (NB - 1)], 1);
    __syncthreads();
    if (t < NB) atomicAdd(&g_counts[t], hc[t]);
}
__global__ void k_scan()
{
    int run = 0, mx = 0;
    for (int b = 0; b < NB; b++) {
        g_starts[b] = run;
        int c = g_counts[b];
        run += c;
        if (c > mx) mx = c;
    }
    g_maxM = mx;
}

// ---- weight split+pack prep: words of [W_in | W_out | Ws^T(s,o,k)] ----
__global__ void k_split_w(const float* __restrict__ W_in, const float* __restrict__ W_out,
                          const float* __restrict__ Ws)
{
    int i = blockIdx.x * blockDim.x + threadIdx.x;
    if (i >= W_WORDS) return;
    int e = 2 * i;
    float w0, w1;
    if (e < 196608) { w0 = W_in[e]; w1 = W_in[e + 1]; }
    else if (e < 262144) { w0 = W_out[e - 196608]; w1 = W_out[e - 196607]; }
    else {
        int j = e - 262144, s = j >> 14, rem = j & 16383;
        int o = rem >> 8, k = rem & 255;
        w0 = Ws[s * 16384 + k * 64 + o];
        w1 = Ws[s * 16384 + (k + 1) * 64 + o];
    }
    split2(w0, w1, g_Whi[i], g_Wlo[i]);
}

// ---- bf16x3 tensor-core GEMM body: C[NN,NTOT] = A[NN,256] * W^T + bias ----
template<int NTOT>
__device__ __forceinline__ void gemm_tc_body(
    const float* __restrict__ A, const unsigned* __restrict__ Whi,
    const unsigned* __restrict__ Wlo, const float* __restrict__ bias,
    float* __restrict__ C)
{
    __shared__ unsigned Ah[64][20], Al[64][20];
    __shared__ unsigned Bh[128][20], Bl[128][20];
    const int tid = threadIdx.x, wid = tid >> 5, lane = tid & 31;
    const int g = lane >> 2, t4 = lane & 3, wm = wid >> 1, wn = wid & 1;
    const int m0 = blockIdx.x * 64, n0 = blockIdx.y * 128;

    float acc[8][4] = {};
    for (int ch = 0; ch < 8; ch++) {
        __syncthreads();
        for (int i = tid; i < 512; i += 256) {            // A chunk 64 x 32
            int r = i >> 3, fc = (i & 7) << 2, w0 = (i & 7) << 1;
            float4 v = *(const float4*)(A + (size_t)(m0 + r) * 256 + ch * 32 + fc);
            split2(v.x, v.y, Ah[r][w0], Al[r][w0]);
            split2(v.z, v.w, Ah[r][w0 + 1], Al[r][w0 + 1]);
        }
        for (int i = tid; i < 1024; i += 256) {           // B chunk 128 x 32 (words)
            int r = i >> 3, w2 = (i & 7) << 1;
            size_t go = (size_t)(n0 + r) * 128 + ch * 16 + w2;
            *(uint2*)&Bh[r][w2] = *(const uint2*)(Whi + go);
            *(uint2*)&Bl[r][w2] = *(const uint2*)(Wlo + go);
        }
        __syncthreads();
#pragma unroll
        for (int kk = 0; kk < 2; kk++) {
            const int kw = kk * 8, ra = 16 * wm + g;
            unsigned ah[4], al[4];
            ah[0] = Ah[ra][kw + t4];     ah[1] = Ah[ra + 8][kw + t4];
            ah[2] = Ah[ra][kw + t4 + 4]; ah[3] = Ah[ra + 8][kw + t4 + 4];
            al[0] = Al[ra][kw + t4];     al[1] = Al[ra + 8][kw + t4];
            al[2] = Al[ra][kw + t4 + 4]; al[3] = Al[ra + 8][kw + t4 + 4];
#pragma unroll
            for (int ni = 0; ni < 8; ni++) {
                int n = 64 * wn + 8 * ni + g;
                unsigned bh0 = Bh[n][kw + t4], bh1 = Bh[n][kw + t4 + 4];
                mma16(acc[ni], ah, bh0, bh1);
                mma16(acc[ni], ah, Bl[n][kw + t4], Bl[n][kw + t4 + 4]);
                mma16(acc[ni], al, bh0, bh1);
            }
        }
    }
    const int r1 = m0 + 16 * wm + g;
#pragma unroll
    for (int ni = 0; ni < 8; ni++) {
        int n = n0 + 64 * wn + 8 * ni + 2 * t4;
        float b0 = bias[n], b1 = bias[n + 1];
        *(float2*)(C + (size_t)r1 * NTOT + n)       = make_float2(acc[ni][0] + b0, acc[ni][1] + b1);
        *(float2*)(C + (size_t)(r1 + 8) * NTOT + n) = make_float2(acc[ni][2] + b0, acc[ni][3] + b1);
    }
}

__global__ void __launch_bounds__(256) k_gemm_qkv_tc(const float* __restrict__ bias)
{ gemm_tc_body<768>(g_h, g_Whi, g_Wlo, bias, g_qkv); }

__global__ void __launch_bounds__(256) k_gemm_out_tc(const float* __restrict__ bias)
{ gemm_tc_body<256>(g_ctx, g_Whi + 98304, g_Wlo + 98304, bias, g_att); }

// ---- scale GEMM: h[:, s*64+o] = (x + spec[s]) * WsT[s] + bs ----
__global__ void __launch_bounds__(256) k_gemm_scale_tc(
    const float* __restrict__ x, const float* __restrict__ spec,
    const float* __restrict__ bs)
{
    __shared__ unsigned Ah[64][20], Al[64][20];
    __shared__ unsigned Bh[64][20], Bl[64][20];
    const int tid = threadIdx.x, wid = tid >> 5, lane = tid & 31;
    const int g = lane >> 2, t4 = lane & 3, wm = wid >> 1, wn = wid & 1;
    const int m0 = blockIdx.x * 64;

    for (int s = 0; s < NSC; s++) {
        const float* sb = spec + (size_t)s * NN * 256;
        const unsigned* Wsh = g_Whi + 131072 + s * 8192;
        const unsigned* Wsl = g_Wlo + 131072 + s * 8192;
        float acc[4][4] = {};
        for (int ch = 0; ch < 8; ch++) {
            __syncthreads();
            for (int i = tid; i < 512; i += 256) {
                int r = i >> 3, fc = (i & 7) << 2, w0 = (i & 7) << 1;
                size_t go = (size_t)(m0 + r) * 256 + ch * 32 + fc;
                float4 a = *(const float4*)(x + go);
                float4 b = *(const float4*)(sb + go);
                a.x += b.x; a.y += b.y; a.z += b.z; a.w += b.w;
                split2(a.x, a.y, Ah[r][w0], Al[r][w0]);
                split2(a.z, a.w, Ah[r][w0 + 1], Al[r][w0 + 1]);
            }
            for (int i = tid; i < 512; i += 256) {
                int r = i >> 3, w2 = (i & 7) << 1;
                size_t go = (size_t)r * 128 + ch * 16 + w2;
                *(uint2*)&Bh[r][w2] = *(const uint2*)(Wsh + go);
                *(uint2*)&Bl[r][w2] = *(const uint2*)(Wsl + go);
            }
            __syncthreads();
#pragma unroll
            for (int kk = 0; kk < 2; kk++) {
                const int kw = kk * 8, ra = 16 * wm + g;
                unsigned ah[4], al[4];
                ah[0] = Ah[ra][kw + t4];     ah[1] = Ah[ra + 8][kw + t4];
                ah[2] = Ah[ra][kw + t4 + 4]; ah[3] = Ah[ra + 8][kw + t4 + 4];
                al[0] = Al[ra][kw + t4];     al[1] = Al[ra + 8][kw + t4];
                al[2] = Al[ra][kw + t4 + 4]; al[3] = Al[ra + 8][kw + t4 + 4];
#pragma unroll
                for (int ni = 0; ni < 4; ni++) {
                    int n = 32 * wn + 8 * ni + g;
                    unsigned bh0 = Bh[n][kw + t4], bh1 = Bh[n][kw + t4 + 4];
                    mma16(acc[ni], ah, bh0, bh1);
                    mma16(acc[ni], ah, Bl[n][kw + t4], Bl[n][kw + t4 + 4]);
                    mma16(acc[ni], al, bh0, bh1);
                }
            }
        }
        const int r1 = m0 + 16 * wm + g;
#pragma unroll
        for (int ni = 0; ni < 4; ni++) {
            int col = 32 * wn + 8 * ni + 2 * t4, n = s * 64 + col;
            float b0 = bs[n], b1 = bs[n + 1];
            *(float2*)(g_h + (size_t)r1 * 256 + n)       = make_float2(acc[ni][0] + b0, acc[ni][1] + b1);
            *(float2*)(g_h + (size_t)(r1 + 8) * 256 + n) = make_float2(acc[ni][2] + b0, acc[ni][3] + b1);
        }
        __syncthreads();
    }
}

// ---- flash attention (bf16x3): grid (NB, NH, 24) — one 64-row q-tile per
// block (q0 = 64*blockIdx.z, early-exit when q0 >= c). 128 threads, K/V tile
// 32. Pad keys of the reference (no key-padding mask) folded analytically
// with multiplicity (maxM - c).
__global__ void __launch_bounds__(128) k_attn_tc(const float* __restrict__ b_in)
{
    __shared__ unsigned      Qh[64][20], Ql[64][20];
    __shared__ unsigned      Kh[32][20], Kl[32][20];
    __shared__ __nv_bfloat16 Vh[32][40], Vl[32][40];   // d-major: [d][key]
    __shared__ unsigned      Pm[4][16][20], Pl[4][16][20];
    __shared__ float         kp[32], vp[32];

    const int b = blockIdx.x, h = blockIdx.y;
    const int c = g_counts[b], start = g_starts[b];
    const int q0 = blockIdx.z * 64;
    if (q0 >= c) return;
    const int tid = threadIdx.x, wid = tid >> 5, lane = tid & 31;
    const int g = lane >> 2, t4 = lane & 3;
    const float npadf = (float)(g_maxM - c);
    const float qs = 0.17677669529663687f;

    if (tid < 32) { kp[tid] = b_in[E + h * HD + tid]; vp[tid] = b_in[2 * E + h * HD + tid]; }

    for (int i = tid; i < 512; i += 128) {            // Q tile 64 x 32
        int r = i >> 3, fc = (i & 7) << 2, w0 = (i & 7) << 1, row = q0 + r;
        float4 v = make_float4(0.f, 0.f, 0.f, 0.f);
        if (row < c) v = *(const float4*)(g_qkv + (size_t)(start + row) * 768 + h * HD + fc);
        v.x *= qs; v.y *= qs; v.z *= qs; v.w *= qs;
        split2(v.x, v.y, Qh[r][w0], Ql[r][w0]);
        split2(v.z, v.w, Qh[r][w0 + 1], Ql[r][w0 + 1]);
    }
    float m1 = -1e30f, m2 = -1e30f, l1 = 0.f, l2 = 0.f;
    float acc[4][4] = {};

    for (int kb = 0; kb < c; kb += 32) {
        __syncthreads();
        for (int i = tid; i < 256; i += 128) {        // K/V chunk 32 x 32
            int r = i >> 3, fc = (i & 7) << 2, w0 = (i & 7) << 1, key = kb + r;
            float4 kv = make_float4(0.f, 0.f, 0.f, 0.f);
            float4 vv = make_float4(0.f, 0.f, 0.f, 0.f);
            if (key < c) {
                size_t base = (size_t)(start + key) * 768 + h * HD + fc;
                kv = *(const float4*)(g_qkv + base + E);
                vv = *(const float4*)(g_qkv + base + 2 * E);
            }
            split2(kv.x, kv.y, Kh[r][w0], Kl[r][w0]);
            split2(kv.z, kv.w, Kh[r][w0 + 1], Kl[r][w0 + 1]);
            float vs[4] = {vv.x, vv.y, vv.z, vv.w};
#pragma unroll
            for (int j = 0; j < 4; j++) {
                __nv_bfloat16 hb = __float2bfloat16_rn(vs[j]);
                Vh[fc + j][r] = hb;
                Vl[fc + j][r] = __float2bfloat16_rn(vs[j] - __bfloat162float(hb));
            }
        }
        __syncthreads();

        float s[4][4] = {};
        const int qr = 16 * wid + g;
#pragma unroll
        for (int kk = 0; kk < 2; kk++) {
            const int kw = kk * 8;
            unsigned ah[4], al[4];
            ah[0] = Qh[qr][kw + t4];     ah[1] = Qh[qr + 8][kw + t4];
            ah[2] = Qh[qr][kw + t4 + 4]; ah[3] = Qh[qr + 8][kw + t4 + 4];
            al[0] = Ql[qr][kw + t4];     al[1] = Ql[qr + 8][kw + t4];
            al[2] = Ql[qr][kw + t4 + 4]; al[3] = Ql[qr + 8][kw + t4 + 4];
#pragma unroll
            for (int ni = 0; ni < 4; ni++) {
                int key = 8 * ni + g;
                unsigned bh0 = Kh[key][kw + t4], bh1 = Kh[key][kw + t4 + 4];
                mma16(s[ni], ah, bh0, bh1);
                mma16(s[ni], ah, Kl[key][kw + t4], Kl[key][kw + t4 + 4]);
                mma16(s[ni], al, bh0, bh1);
            }
        }
#pragma unroll
        for (int ni = 0; ni < 4; ni++) {
            int col = kb + 8 * ni + 2 * t4;
            if (col >= c)     { s[ni][0] = -1e30f; s[ni][2] = -1e30f; }
            if (col + 1 >= c) { s[ni][1] = -1e30f; s[ni][3] = -1e30f; }
        }
        float mx1 = -1e30f, mx2 = -1e30f;
#pragma unroll
        for (int ni = 0; ni < 4; ni++) {
            mx1 = fmaxf(mx1, fmaxf(s[ni][0], s[ni][1]));
            mx2 = fmaxf(mx2, fmaxf(s[ni][2], s[ni][3]));
        }
        mx1 = fmaxf(mx1, __shfl_xor_sync(~0u, mx1, 1)); mx1 = fmaxf(mx1, __shfl_xor_sync(~0u, mx1, 2));
        mx2 = fmaxf(mx2, __shfl_xor_sync(~0u, mx2, 1)); mx2 = fmaxf(mx2, __shfl_xor_sync(~0u, mx2, 2));
        float nm1 = fmaxf(m1, mx1), nm2 = fmaxf(m2, mx2);
        float corr1 = __expf(m1 - nm1), corr2 = __expf(m2 - nm2);
        float sum1 = 0.f, sum2 = 0.f;
#pragma unroll
        for (int ni = 0; ni < 4; ni++) {
            float p0 = __expf(s[ni][0] - nm1), p1 = __expf(s[ni][1] - nm1);
            float p2 = __expf(s[ni][2] - nm2), p3 = __expf(s[ni][3] - nm2);
            sum1 += p0 + p1; sum2 += p2 + p3;
            int w = 4 * ni + t4;
            split2(p0, p1, Pm[wid][g][w], Pl[wid][g][w]);
            split2(p2, p3, Pm[wid][g + 8][w], Pl[wid][g + 8][w]);
        }
        sum1 += __shfl_xor_sync(~0u, sum1, 1); sum1 += __shfl_xor_sync(~0u, sum1, 2);
        sum2 += __shfl_xor_sync(~0u, sum2, 1); sum2 += __shfl_xor_sync(~0u, sum2, 2);
        l1 = l1 * corr1 + sum1; l2 = l2 * corr2 + sum2;
#pragma unroll
        for (int nd = 0; nd < 4; nd++) {
            acc[nd][0] *= corr1; acc[nd][1] *= corr1;
            acc[nd][2] *= corr2; acc[nd][3] *= corr2;
        }
        m1 = nm1; m2 = nm2;
        __syncwarp();
#pragma unroll
        for (int kk = 0; kk < 2; kk++) {
            const int kw = kk * 8;
            unsigned ph[4], pl[4];
            ph[0] = Pm[wid][g][kw + t4];     ph[1] = Pm[wid][g + 8][kw + t4];
            ph[2] = Pm[wid][g][kw + t4 + 4]; ph[3] = Pm[wid][g + 8][kw + t4 + 4];
            pl[0] = Pl[wid][g][kw + t4];     pl[1] = Pl[wid][g + 8][kw + t4];
            pl[2] = Pl[wid][g][kw + t4 + 4]; pl[3] = Pl[wid][g + 8][kw + t4 + 4];
#pragma unroll
            for (int nd = 0; nd < 4; nd++) {
                int d = 8 * nd + g;
                unsigned vh0 = *(const unsigned*)&Vh[d][2 * (kw + t4)];
                unsigned vh1 = *(const unsigned*)&Vh[d][2 * (kw + t4 + 4)];
                mma16(acc[nd], ph, vh0, vh1);
                mma16(acc[nd], ph, *(const unsigned*)&Vl[d][2 * (kw + t4)],
                                   *(const unsigned*)&Vl[d][2 * (kw + t4 + 4)]);
                mma16(acc[nd], pl, vh0, vh1);
            }
        }
        __syncwarp();
    }

    if (npadf > 0.f) {
        const int qr = 16 * wid + g;
        float d1 = 0.f, d2 = 0.f;
#pragma unroll
        for (int jw = 0; jw < 4; jw++) {
            int w = t4 + jw * 4;
            unsigned uh1 = Qh[qr][w], ul1 = Ql[qr][w];
            unsigned uh2 = Qh[qr + 8][w], ul2 = Ql[qr + 8][w];
            d1 += (blo(uh1) + blo(ul1)) * kp[2 * w] + (bhi(uh1) + bhi(ul1)) * kp[2 * w + 1];
            d2 += (blo(uh2) + blo(ul2)) * kp[2 * w] + (bhi(uh2) + bhi(ul2)) * kp[2 * w + 1];
        }
        d1 += __shfl_xor_sync(~0u, d1, 1); d1 += __shfl_xor_sync(~0u, d1, 2);
        d2 += __shfl_xor_sync(~0u, d2, 1); d2 += __shfl_xor_sync(~0u, d2, 2);
        float nm1 = fmaxf(m1, d1), nm2 = fmaxf(m2, d2);
        float corr1 = __expf(m1 - nm1), corr2 = __expf(m2 - nm2);
        float w1 = __expf(d1 - nm1) * npadf, w2 = __expf(d2 - nm2) * npadf;
        l1 = l1 * corr1 + w1; l2 = l2 * corr2 + w2;
#pragma unroll
        for (int nd = 0; nd < 4; nd++) {
            int d0 = 8 * nd + 2 * t4;
            acc[nd][0] = acc[nd][0] * corr1 + w1 * vp[d0];
            acc[nd][1] = acc[nd][1] * corr1 + w1 * vp[d0 + 1];
            acc[nd][2] = acc[nd][2] * corr2 + w2 * vp[d0];
            acc[nd][3] = acc[nd][3] * corr2 + w2 * vp[d0 + 1];
        }
    }
    float inv1 = 1.f / l1, inv2 = 1.f / l2;
    int row1 = q0 + 16 * wid + g, row2 = row1 + 8;
#pragma unroll
    for (int nd = 0; nd < 4; nd++) {
        int d0 = 8 * nd + 2 * t4;
        if (row1 < c)
            *(float2*)(g_ctx + (size_t)(start + row1) * 256 + h * HD + d0) =
                make_float2(acc[nd][0] * inv1, acc[nd][1] * inv1);
        if (row2 < c)
            *(float2*)(g_ctx + (size_t)(start + row2) * 256 + h * HD + d0) =
                make_float2(acc[nd][2] * inv2, acc[nd][3] * inv2);
    }
}

// ---- BatchNorm + ReLU ----
__global__ void k_bn_stats()
{
    const int ch = threadIdx.x, r0 = blockIdx.x * 128;
    float s = 0.f, s2 = 0.f;
    for (int r = 0; r < 128; r++) {
        float v = g_att[(size_t)(r0 + r) * E + ch];
        s += v; s2 += v * v;
    }
    g_psum[blockIdx.x * E + ch] = s;
    g_psumsq[blockIdx.x * E + ch] = s2;
}
__global__ void k_bn_finalize(const float* __restrict__ gamma, const float* __restrict__ beta)
{
    const int ch = threadIdx.x;
    float s = 0.f, s2 = 0.f;
    for (int p = 0; p < 256; p++) { s += g_psum[p * E + ch]; s2 += g_psumsq[p * E + ch]; }
    float mean = s / (float)NN;
    float var = s2 / (float)NN - mean * mean;
    float sc = rsqrtf(var + BN_EPS) * gamma[ch];
    g_bnscale[ch] = sc;
    g_bnshift[ch] = beta[ch] - mean * sc;
}
__global__ void k_bn_apply(float* __restrict__ out)
{
    size_t idx = ((size_t)blockIdx.x * blockDim.x + threadIdx.x) * 4;
    int ch = (int)(idx & (E - 1));
    float4 v = *(const float4*)(g_att + idx);
    float4 r;
    r.x = fmaxf(v.x * g_bnscale[ch] + g_bnshift[ch], 0.f);
    r.y = fmaxf(v.y * g_bnscale[ch + 1] + g_bnshift[ch + 1], 0.f);
    r.z = fmaxf(v.z * g_bnscale[ch + 2] + g_bnshift[ch + 2], 0.f);
    r.w = fmaxf(v.w * g_bnscale[ch + 3] + g_bnshift[ch + 3], 0.f);
    *(float4*)(out + idx) = r;
}

extern "C" void kernel_launch(void* const* d_in, const int* in_sizes, int n_in,
                              void* d_out, int out_size)
{
    const float* x        = (const float*)d_in[0];
    const float* spectral = (const float*)d_in[1];
    const float* Ws       = (const float*)d_in[2];
    const float* bs       = (const float*)d_in[3];
    const float* W_in     = (const float*)d_in[4];
    const float* b_in     = (const float*)d_in[5];
    const float* W_out    = (const float*)d_in[6];
    const float* b_out    = (const float*)d_in[7];
    const float* gamma    = (const float*)d_in[8];
    const float* beta     = (const float*)d_in[9];
    const int*   batch32  = (const int*)d_in[10];
    float* out = (float*)d_out;

    k_detect<<<1, 256>>>(batch32);
    k_hist<<<NN / 256, 256>>>(batch32);
    k_scan<<<1, 1>>>();
    k_split_w<<<W_WORDS / 256, 256>>>(W_in, W_out, Ws);

    k_gemm_scale_tc<<<NN / 64, 256>>>(x, spectral, bs);
    k_gemm_qkv_tc<<<dim3(NN / 64, 6), 256>>>(b_in);
    k_attn_tc<<<dim3(NB, NH, 24), 128>>>(b_in);
    k_gemm_out_tc<<<dim3(NN / 64, 2), 256>>>(b_out);

    k_bn_stats<<<256, 256>>>();
    k_bn_finalize<<<1, 256>>>(gamma, beta);
    k_bn_apply<<<(NN * E / 4) / 256, 256>>>(out);
}